// round 1
// baseline (speedup 1.0000x reference)
#include <cuda_runtime.h>
#include <math.h>

#define NB    32
#define NF    500
#define FEAT  256
#define COUT  2
#define CIN   2
#define KK    16
#define FRAME 160
#define OVL   40
#define NSAMP (NF * FRAME)          // 80000
#define NFILT (COUT * CIN * KK)     // 64
#define NOUT  (NFILT + COUT)        // 66

// shape_gain = 10^(-6/20), gain_a = 6 * ln(10)/20, gain_b = 0
#define GAIN_A 0.69077552789821368f
#define SG     0.50118723362727224f
#define OMSG   0.49881276637272776f

// Per-frame filters (already normalized, identity-mixed, gain-scaled):
// layout [(b*NF + f)*64 + cout*32 + cin*16 + k]  -> 4 MB scratch
__device__ float g_w[(size_t)NB * NF * NFILT];

// ---------------------------------------------------------------------------
// Kernel A: per-frame filter synthesis.
// One block per (b,f). 8 warps; each warp computes dot(feat_row, W_row) for
// outputs o = wid, wid+8, ... (66 outputs = 64 conv taps + 2 gain logits),
// via float4 loads + warp shuffle reduce. Then normalize per cout over the
// 32 (cin,k) taps, mix with identity tap k=7, apply exp(a*tanh(g)) gain.
// ---------------------------------------------------------------------------
__global__ void __launch_bounds__(256) filt_kernel(
    const float* __restrict__ feat,
    const float* __restrict__ ckw,  // (64, 256)
    const float* __restrict__ ckb,  // (64,)
    const float* __restrict__ fgw,  // (2, 256)
    const float* __restrict__ fgb)  // (2,)
{
    int bf = blockIdx.x;                       // b*NF + f
    const float* frow = feat + (size_t)bf * FEAT;

    __shared__ float4 fs4[FEAT / 4];
    __shared__ float  raw[NOUT];
    __shared__ float  invn[COUT], gainv[COUT];

    int tid  = threadIdx.x;
    int lane = tid & 31;
    int wid  = tid >> 5;

    if (tid < FEAT / 4) fs4[tid] = ((const float4*)frow)[tid];
    __syncthreads();

    float4 f0 = fs4[lane];
    float4 f1 = fs4[lane + 32];

    for (int o = wid; o < NOUT; o += 8) {
        const float4* wr = (o < NFILT)
            ? (const float4*)(ckw + (size_t)o * FEAT)
            : (const float4*)(fgw + (size_t)(o - NFILT) * FEAT);
        float4 w0 = wr[lane];
        float4 w1 = wr[lane + 32];
        float s = f0.x * w0.x + f0.y * w0.y + f0.z * w0.z + f0.w * w0.w
                + f1.x * w1.x + f1.y * w1.y + f1.z * w1.z + f1.w * w1.w;
        #pragma unroll
        for (int off = 16; off; off >>= 1)
            s += __shfl_down_sync(0xffffffffu, s, off);
        if (lane == 0)
            raw[o] = s + ((o < NFILT) ? ckb[o] : fgb[o - NFILT]);
    }
    __syncthreads();

    if (tid < COUT) {
        float ss = 0.f;
        #pragma unroll
        for (int i = 0; i < CIN * KK; ++i) {
            float v = raw[tid * CIN * KK + i];
            ss += v * v;
        }
        invn[tid]  = 1.0f / (1e-6f + sqrtf(ss));
        gainv[tid] = expf(GAIN_A * tanhf(raw[NFILT + tid]));  // gain_b == 0
    }
    __syncthreads();

    if (tid < NFILT) {
        int cout = tid >> 5;          // /(CIN*KK)
        int k    = tid & (KK - 1);
        float v  = SG * raw[tid] * invn[cout];
        if (k == KK - 1 - KK / 2) v += OMSG;   // identity tap (k=7)
        g_w[(size_t)bf * NFILT + tid] = v * gainv[cout];
    }
}

// ---------------------------------------------------------------------------
// Kernel B: time-domain adaptive conv + overlap-add crossfade.
// Block = one (b, f); 160 threads = 160 output samples of the frame head.
// out[f*160 + j] = win1[j<40]*conv(x, w_f)[j] + (f>0 && j<40)*win2[j]*conv(x, w_{f-1})[160+j]
// Both terms read identical x samples x[f*160 + j - k], so one shared
// 175-sample window + two 64-float filter sets suffice.
// ---------------------------------------------------------------------------
__global__ void __launch_bounds__(FRAME) conv_kernel(
    const float* __restrict__ x,     // (B, CIN, NSAMP)
    const float* __restrict__ owin,  // (40,)
    float* __restrict__ out)         // (B, COUT, NSAMP)
{
    int f = blockIdx.x;
    int b = blockIdx.y;

    __shared__ float xs[CIN][FRAME + KK];      // 175 used, 176 padded
    __shared__ float wc[COUT][CIN][KK];        // current frame filter
    __shared__ float wp[COUT][CIN][KK];        // previous frame filter
    __shared__ float w1s[OVL], w2s[OVL];

    int tid  = threadIdx.x;
    int base = f * FRAME - (KK - 1);
    const float* xb = x + (size_t)b * CIN * NSAMP;

    const int WLEN = FRAME + KK - 1;           // 175
    for (int i = tid; i < CIN * WLEN; i += FRAME) {
        int cin = i / WLEN;
        int idx = i - cin * WLEN;
        int p   = base + idx;
        xs[cin][idx] = (p >= 0 && p < NSAMP) ? xb[(size_t)cin * NSAMP + p] : 0.f;
    }

    const float* wf = g_w + ((size_t)b * NF + f) * NFILT;
    if (tid < NFILT)
        ((float*)wc)[tid] = wf[tid];
    else if (tid < 2 * NFILT)
        ((float*)wp)[tid - NFILT] = (f > 0) ? wf[tid - 2 * NFILT] : 0.f;
    if (tid < OVL) {
        w2s[tid] = owin[tid];
        w1s[tid] = owin[OVL - 1 - tid];
    }
    __syncthreads();

    int j = tid;
    float a0 = 0.f, a1 = 0.f;
    #pragma unroll
    for (int cin = 0; cin < CIN; ++cin) {
        #pragma unroll
        for (int k = 0; k < KK; ++k) {
            float xv = xs[cin][j + (KK - 1) - k];
            a0 = fmaf(xv, wc[0][cin][k], a0);
            a1 = fmaf(xv, wc[1][cin][k], a1);
        }
    }

    size_t op = (size_t)b * COUT * NSAMP + (size_t)f * FRAME + j;
    if (j < OVL) {
        float p0 = 0.f, p1 = 0.f;
        #pragma unroll
        for (int cin = 0; cin < CIN; ++cin) {
            #pragma unroll
            for (int k = 0; k < KK; ++k) {
                float xv = xs[cin][j + (KK - 1) - k];
                p0 = fmaf(xv, wp[0][cin][k], p0);
                p1 = fmaf(xv, wp[1][cin][k], p1);
            }
        }
        float m1 = w1s[j], m2 = w2s[j];
        out[op]         = m1 * a0 + m2 * p0;   // wp==0 at f==0 -> no tail
        out[op + NSAMP] = m1 * a1 + m2 * p1;
    } else {
        out[op]         = a0;
        out[op + NSAMP] = a1;
    }
}

extern "C" void kernel_launch(void* const* d_in, const int* in_sizes, int n_in,
                              void* d_out, int out_size)
{
    const float* x    = (const float*)d_in[0];  // (32, 2, 80000)
    const float* feat = (const float*)d_in[1];  // (32, 500, 256)
    const float* ckw  = (const float*)d_in[2];  // (64, 256)
    const float* ckb  = (const float*)d_in[3];  // (64,)
    const float* fgw  = (const float*)d_in[4];  // (2, 256)
    const float* fgb  = (const float*)d_in[5];  // (2,)
    const float* ow   = (const float*)d_in[6];  // (40,)
    float* out = (float*)d_out;                 // (32, 2, 80000)

    filt_kernel<<<NB * NF, 256>>>(feat, ckw, ckb, fgw, fgb);
    conv_kernel<<<dim3(NF, NB), FRAME>>>(x, ow, out);
}

// round 2
// speedup vs baseline: 1.8202x; 1.8202x over previous
#include <cuda_runtime.h>
#include <math.h>

#define NB    32
#define NF    500
#define FEAT  256
#define COUT  2
#define CIN   2
#define KK    16
#define FRAME 160
#define OVL   40
#define NSAMP (NF * FRAME)          // 80000
#define NFILT (COUT * CIN * KK)     // 64

#define GAIN_A 0.69077552789821368f
#define SG     0.50118723362727224f
#define OMSG   0.49881276637272776f

// Per-frame filters: [(b*NF+f)*64 + cout*32 + cin*16 + k]
__device__ float g_w[(size_t)NB * NF * NFILT];

// ===========================================================================
// Kernel A: filter synthesis GEMM + epilogue.
// Grid 125 blocks; block = 128 feature rows x 64 outputs.
// Thread tile: 8 rows x 4 outs. feat tile row-major (broadcast LDS.128),
// W transposed [fe][o] (conflict-free LDS.128). FMA-bound.
// ===========================================================================
#define TBF 128
#define FSTRIDE4 65                  // fs row stride in float4 (260 floats)
#define WSTRIDE  68                  // Wt row stride in floats

__global__ void __launch_bounds__(256) filt_kernel(
    const float* __restrict__ feat,
    const float* __restrict__ ckw,  // (64, 256)
    const float* __restrict__ ckb,  // (64,)
    const float* __restrict__ fgw,  // (2, 256)
    const float* __restrict__ fgb)  // (2,)
{
    extern __shared__ float sm[];
    float*  fs   = sm;                                   // [128][260]
    float*  Wt   = sm + TBF * 260;                       // [256][68]
    float*  gg   = Wt + 256 * WSTRIDE;                   // graw [128][2]
    float*  invn = gg + TBF * 2;                         // [128][2]
    float*  gain = invn + TBF * 2;                       // [128][2]
    float4* fs4  = (float4*)fs;
    float4* Wt4  = (float4*)Wt;

    int tid = threadIdx.x;
    int bf0 = blockIdx.x * TBF;

    // ---- load feat tile (row-major, coalesced) ----
    const float4* feat4 = (const float4*)feat;
    for (int i = tid; i < TBF * 64; i += 256) {
        int r = i >> 6, c4 = i & 63;
        fs4[r * FSTRIDE4 + c4] = feat4[(size_t)(bf0 + r) * 64 + c4];
    }
    // ---- load W transposed ----
    for (int i = tid; i < 64 * 256; i += 256) {
        int o = i >> 8, fe = i & 255;
        Wt[fe * WSTRIDE + o] = ckw[i];
    }
    // cols 64..67 of Wt: zero (unused by main loop)
    {
        int fe = tid;
        Wt[fe * WSTRIDE + 64] = 0.f; Wt[fe * WSTRIDE + 65] = 0.f;
        Wt[fe * WSTRIDE + 66] = 0.f; Wt[fe * WSTRIDE + 67] = 0.f;
    }
    __syncthreads();

    // ---- main GEMM: 8 rows x 4 outs per thread ----
    int ogrp = tid & 15;             // 16 groups of 4 outs
    int rgrp = tid >> 4;             // 16 groups of 8 rows
    int o0 = ogrp * 4;
    int r0 = rgrp * 8;

    float acc[8][4];
    #pragma unroll
    for (int i = 0; i < 8; ++i)
        #pragma unroll
        for (int j = 0; j < 4; ++j) acc[i][j] = 0.f;

    const float4* fsp = fs4 + r0 * FSTRIDE4;
    const float4* wtp = Wt4 + ogrp;              // Wt4 row stride = 17

    #pragma unroll 4
    for (int fe4 = 0; fe4 < 64; ++fe4) {
        float4 fv[8];
        #pragma unroll
        for (int i = 0; i < 8; ++i) fv[i] = fsp[i * FSTRIDE4 + fe4];
        float4 w0 = wtp[(4 * fe4 + 0) * 17];
        float4 w1 = wtp[(4 * fe4 + 1) * 17];
        float4 w2 = wtp[(4 * fe4 + 2) * 17];
        float4 w3 = wtp[(4 * fe4 + 3) * 17];
        #pragma unroll
        for (int i = 0; i < 8; ++i) {
            acc[i][0] = fmaf(fv[i].x, w0.x, acc[i][0]);
            acc[i][1] = fmaf(fv[i].x, w0.y, acc[i][1]);
            acc[i][2] = fmaf(fv[i].x, w0.z, acc[i][2]);
            acc[i][3] = fmaf(fv[i].x, w0.w, acc[i][3]);
            acc[i][0] = fmaf(fv[i].y, w1.x, acc[i][0]);
            acc[i][1] = fmaf(fv[i].y, w1.y, acc[i][1]);
            acc[i][2] = fmaf(fv[i].y, w1.z, acc[i][2]);
            acc[i][3] = fmaf(fv[i].y, w1.w, acc[i][3]);
            acc[i][0] = fmaf(fv[i].z, w2.x, acc[i][0]);
            acc[i][1] = fmaf(fv[i].z, w2.y, acc[i][1]);
            acc[i][2] = fmaf(fv[i].z, w2.z, acc[i][2]);
            acc[i][3] = fmaf(fv[i].z, w2.w, acc[i][3]);
            acc[i][0] = fmaf(fv[i].w, w3.x, acc[i][0]);
            acc[i][1] = fmaf(fv[i].w, w3.y, acc[i][1]);
            acc[i][2] = fmaf(fv[i].w, w3.z, acc[i][2]);
            acc[i][3] = fmaf(fv[i].w, w3.w, acc[i][3]);
        }
    }

    // ---- gain logits: thread t -> (row tid>>1, cout tid&1), dot from smem+L2 ----
    {
        int r = tid >> 1, c = tid & 1;
        const float4* fr = fs4 + r * FSTRIDE4;
        const float4* gw = (const float4*)fgw + c * 64;
        float s = 0.f;
        #pragma unroll 4
        for (int fe4 = 0; fe4 < 64; ++fe4) {
            float4 a = fr[fe4];
            float4 b = __ldg(&gw[fe4]);
            s += a.x * b.x + a.y * b.y + a.z * b.z + a.w * b.w;
        }
        gg[r * 2 + c] = s + __ldg(&fgb[c]);
    }
    __syncthreads();

    // ---- store raw (with bias) into reused fs region ----
    float* raw = fs;                  // [128][68]
    #pragma unroll
    for (int i = 0; i < 8; ++i)
        #pragma unroll
        for (int j = 0; j < 4; ++j)
            raw[(r0 + i) * WSTRIDE + (o0 + j)] = acc[i][j] + __ldg(&ckb[o0 + j]);
    __syncthreads();

    // ---- per (row,cout) norm + gain ----
    {
        int r = tid >> 1, c = tid & 1;
        float ss = 0.f;
        #pragma unroll
        for (int i = 0; i < 32; ++i) {
            float v = raw[r * WSTRIDE + c * 32 + i];
            ss += v * v;
        }
        invn[r * 2 + c] = 1.0f / (1e-6f + sqrtf(ss));
        gain[r * 2 + c] = expf(GAIN_A * tanhf(gg[r * 2 + c]));
    }
    __syncthreads();

    // ---- final scaled filters, coalesced store ----
    for (int idx = tid; idx < TBF * NFILT; idx += 256) {
        int r = idx >> 6, o = idx & 63;
        int co = o >> 5;
        float v = SG * raw[r * WSTRIDE + o] * invn[r * 2 + co];
        if ((o & 15) == 7) v += OMSG;           // identity tap k=7
        g_w[(size_t)(bf0 + r) * NFILT + o] = v * gain[r * 2 + co];
    }
}

// ===========================================================================
// Kernel B: adaptive conv + overlap-add. Warp = one frame; lane = 5 consecutive
// head outputs from a 20-float register window. Tail (40 overlap outputs,
// previous frame's filter) distributed 1..2 per lane, exchanged via smem.
// Outputs staged in smem -> coalesced STG.128.
// ===========================================================================
#define FPB 5
#define WS  824                       // xs row alloc (>= FPB*160+16)

__global__ void __launch_bounds__(FPB * 32) conv_kernel(
    const float* __restrict__ x,     // (B, CIN, NSAMP)
    const float* __restrict__ owin,  // (40,)
    float* __restrict__ out)         // (B, COUT, NSAMP)
{
    __shared__ __align__(16) float xs[CIN][WS];            // origin = f0*160 - 16
    __shared__ __align__(16) float wsm[FPB + 1][NFILT];    // [0]=prev filter
    __shared__ float tb[FPB][COUT][OVL];
    __shared__ __align__(16) float ob[FPB][COUT][FRAME];
    __shared__ float w1s[OVL], w2s[OVL];

    int f0 = blockIdx.x * FPB;
    int b  = blockIdx.y;
    int tid  = threadIdx.x;
    int lane = tid & 31;
    int w    = tid >> 5;              // warp = frame index within block

    // ---- cooperative loads ----
    const float* xb = x + (size_t)b * CIN * NSAMP;
    int base = f0 * FRAME - 16;
    const int NEED = FPB * FRAME + 16;          // [-16, +FPB*160)
    for (int i = tid; i < CIN * NEED; i += FPB * 32) {
        int cin = i / NEED;
        int idx = i - cin * NEED;
        int p   = base + idx;
        xs[cin][idx] = (p >= 0 && p < NSAMP) ? xb[(size_t)cin * NSAMP + p] : 0.f;
    }
    for (int i = tid; i < (FPB + 1) * NFILT; i += FPB * 32) {
        int fidx = f0 - 1 + (i >> 6);
        wsm[0][i] = (fidx >= 0) ? g_w[((size_t)b * NF + fidx) * NFILT + (i & 63)] : 0.f;
    }
    if (tid < OVL) {
        w2s[tid] = owin[tid];
        w1s[tid] = owin[OVL - 1 - tid];
    }
    __syncthreads();

    // ---- head: lane l -> outputs j0..j0+4 ----
    int j0 = 5 * lane;
    int sbase = w * FRAME + 16;       // xs index of this frame's sample 0

    float xw[CIN][20];
    #pragma unroll
    for (int ci = 0; ci < CIN; ++ci)
        #pragma unroll
        for (int i = 0; i < 20; ++i)
            xw[ci][i] = xs[ci][sbase + j0 - 15 + i];

    float head[COUT][5];
    #pragma unroll
    for (int co = 0; co < COUT; ++co)
        #pragma unroll
        for (int m = 0; m < 5; ++m) head[co][m] = 0.f;

    const float4* wc4 = (const float4*)wsm[w + 1];
    #pragma unroll
    for (int co = 0; co < COUT; ++co) {
        #pragma unroll
        for (int ci = 0; ci < CIN; ++ci) {
            float4 a = wc4[(co * 32 + ci * 16) / 4 + 0];
            float4 bq = wc4[(co * 32 + ci * 16) / 4 + 1];
            float4 cq = wc4[(co * 32 + ci * 16) / 4 + 2];
            float4 dq = wc4[(co * 32 + ci * 16) / 4 + 3];
            float wk[16] = {a.x,a.y,a.z,a.w, bq.x,bq.y,bq.z,bq.w,
                            cq.x,cq.y,cq.z,cq.w, dq.x,dq.y,dq.z,dq.w};
            #pragma unroll
            for (int m = 0; m < 5; ++m)
                #pragma unroll
                for (int k = 0; k < 16; ++k)
                    head[co][m] = fmaf(wk[k], xw[ci][m + 15 - k], head[co][m]);
        }
    }

    // ---- tail: prev-frame filter at overlap positions, 1-2 per lane ----
    const float4* wp4 = (const float4*)wsm[w];
    {
        float tw[CIN][16];
        #pragma unroll
        for (int ci = 0; ci < CIN; ++ci)
            #pragma unroll
            for (int i = 0; i < 16; ++i)
                tw[ci][i] = xs[ci][sbase + lane - 15 + i];   // j = lane
        float t0 = 0.f, t1 = 0.f;
        #pragma unroll
        for (int ci = 0; ci < CIN; ++ci) {
            float4 a = wp4[(0 * 32 + ci * 16) / 4 + 0];
            float4 bq = wp4[(0 * 32 + ci * 16) / 4 + 1];
            float4 cq = wp4[(0 * 32 + ci * 16) / 4 + 2];
            float4 dq = wp4[(0 * 32 + ci * 16) / 4 + 3];
            float wk[16] = {a.x,a.y,a.z,a.w, bq.x,bq.y,bq.z,bq.w,
                            cq.x,cq.y,cq.z,cq.w, dq.x,dq.y,dq.z,dq.w};
            #pragma unroll
            for (int k = 0; k < 16; ++k)
                t0 = fmaf(wk[k], tw[ci][15 - k], t0);
        }
        #pragma unroll
        for (int ci = 0; ci < CIN; ++ci) {
            float4 a = wp4[(1 * 32 + ci * 16) / 4 + 0];
            float4 bq = wp4[(1 * 32 + ci * 16) / 4 + 1];
            float4 cq = wp4[(1 * 32 + ci * 16) / 4 + 2];
            float4 dq = wp4[(1 * 32 + ci * 16) / 4 + 3];
            float wk[16] = {a.x,a.y,a.z,a.w, bq.x,bq.y,bq.z,bq.w,
                            cq.x,cq.y,cq.z,cq.w, dq.x,dq.y,dq.z,dq.w};
            #pragma unroll
            for (int k = 0; k < 16; ++k)
                t1 = fmaf(wk[k], tw[ci][15 - k], t1);
        }
        if (lane < OVL) { tb[w][0][lane] = t0; tb[w][1][lane] = t1; }
    }
    if (lane < 8) {                                       // j = 32 + lane
        float tw[CIN][16];
        #pragma unroll
        for (int ci = 0; ci < CIN; ++ci)
            #pragma unroll
            for (int i = 0; i < 16; ++i)
                tw[ci][i] = xs[ci][sbase + 32 + lane - 15 + i];
        #pragma unroll
        for (int co = 0; co < COUT; ++co) {
            float t = 0.f;
            #pragma unroll
            for (int ci = 0; ci < CIN; ++ci) {
                const float* wk = wsm[w] + co * 32 + ci * 16;
                #pragma unroll
                for (int k = 0; k < 16; ++k)
                    t = fmaf(wk[k], tw[ci][15 - k], t);
            }
            tb[w][co][32 + lane] = t;
        }
    }
    __syncwarp();

    // ---- combine + stage ----
    #pragma unroll
    for (int co = 0; co < COUT; ++co) {
        #pragma unroll
        for (int m = 0; m < 5; ++m) {
            int j = j0 + m;
            float v = head[co][m];
            if (j < OVL) v = w1s[j] * v + w2s[j] * tb[w][co][j];
            ob[w][co][j] = v;
        }
    }
    __syncwarp();

    // ---- coalesced store ----
    int f = f0 + w;
    #pragma unroll
    for (int co = 0; co < COUT; ++co) {
        float4* op = (float4*)(out + (size_t)b * COUT * NSAMP
                               + (size_t)co * NSAMP + (size_t)f * FRAME);
        const float4* obp = (const float4*)ob[w][co];
        for (int i = lane; i < FRAME / 4; i += 32)
            op[i] = obp[i];
    }
}

extern "C" void kernel_launch(void* const* d_in, const int* in_sizes, int n_in,
                              void* d_out, int out_size)
{
    const float* x    = (const float*)d_in[0];
    const float* feat = (const float*)d_in[1];
    const float* ckw  = (const float*)d_in[2];
    const float* ckb  = (const float*)d_in[3];
    const float* fgw  = (const float*)d_in[4];
    const float* fgb  = (const float*)d_in[5];
    const float* ow   = (const float*)d_in[6];
    float* out = (float*)d_out;

    // dynamic smem: fs(128*260) + Wt(256*68) + gg/invn/gain (3*256)
    int smem = (TBF * 260 + 256 * WSTRIDE + 3 * TBF * 2) * (int)sizeof(float);
    static int configured = 0;
    if (!configured) {
        cudaFuncSetAttribute(filt_kernel,
                             cudaFuncAttributeMaxDynamicSharedMemorySize, smem);
        configured = 1;
    }

    filt_kernel<<<NB * NF / TBF, 256, smem>>>(feat, ckw, ckb, fgw, fgb);
    conv_kernel<<<dim3(NF / FPB, NB), FPB * 32>>>(x, ow, out);
}

// round 3
// speedup vs baseline: 2.1888x; 1.2025x over previous
#include <cuda_runtime.h>
#include <math.h>

#define NB    32
#define NF    500
#define FEAT  256
#define COUT  2
#define CIN   2
#define KK    16
#define FRAME 160
#define OVL   40
#define NSAMP (NF * FRAME)          // 80000
#define NFILT (COUT * CIN * KK)     // 64

#define GAIN_A 0.69077552789821368f
#define SG     0.50118723362727224f
#define OMSG   0.49881276637272776f

// Per-frame filters: [(b*NF+f)*64 + cout*32 + cin*16 + k]
__device__ float g_w[(size_t)NB * NF * NFILT];

// ===========================================================================
// Kernel A: filter synthesis GEMM + epilogue (unchanged from round 2; ~7us).
// ===========================================================================
#define TBF 128
#define FSTRIDE4 65
#define WSTRIDE  68

__global__ void __launch_bounds__(256) filt_kernel(
    const float* __restrict__ feat,
    const float* __restrict__ ckw,
    const float* __restrict__ ckb,
    const float* __restrict__ fgw,
    const float* __restrict__ fgb)
{
    extern __shared__ float sm[];
    float*  fs   = sm;                                   // [128][260]
    float*  Wt   = sm + TBF * 260;                       // [256][68]
    float*  gg   = Wt + 256 * WSTRIDE;
    float*  invn = gg + TBF * 2;
    float*  gain = invn + TBF * 2;
    float4* fs4  = (float4*)fs;
    float4* Wt4  = (float4*)Wt;

    int tid = threadIdx.x;
    int bf0 = blockIdx.x * TBF;

    const float4* feat4 = (const float4*)feat;
    for (int i = tid; i < TBF * 64; i += 256) {
        int r = i >> 6, c4 = i & 63;
        fs4[r * FSTRIDE4 + c4] = feat4[(size_t)(bf0 + r) * 64 + c4];
    }
    for (int i = tid; i < 64 * 256; i += 256) {
        int o = i >> 8, fe = i & 255;
        Wt[fe * WSTRIDE + o] = ckw[i];
    }
    {
        int fe = tid;
        Wt[fe * WSTRIDE + 64] = 0.f; Wt[fe * WSTRIDE + 65] = 0.f;
        Wt[fe * WSTRIDE + 66] = 0.f; Wt[fe * WSTRIDE + 67] = 0.f;
    }
    __syncthreads();

    int ogrp = tid & 15;
    int rgrp = tid >> 4;
    int o0 = ogrp * 4;
    int r0 = rgrp * 8;

    float acc[8][4];
    #pragma unroll
    for (int i = 0; i < 8; ++i)
        #pragma unroll
        for (int j = 0; j < 4; ++j) acc[i][j] = 0.f;

    const float4* fsp = fs4 + r0 * FSTRIDE4;
    const float4* wtp = Wt4 + ogrp;

    #pragma unroll 4
    for (int fe4 = 0; fe4 < 64; ++fe4) {
        float4 fv[8];
        #pragma unroll
        for (int i = 0; i < 8; ++i) fv[i] = fsp[i * FSTRIDE4 + fe4];
        float4 w0 = wtp[(4 * fe4 + 0) * 17];
        float4 w1 = wtp[(4 * fe4 + 1) * 17];
        float4 w2 = wtp[(4 * fe4 + 2) * 17];
        float4 w3 = wtp[(4 * fe4 + 3) * 17];
        #pragma unroll
        for (int i = 0; i < 8; ++i) {
            acc[i][0] = fmaf(fv[i].x, w0.x, acc[i][0]);
            acc[i][1] = fmaf(fv[i].x, w0.y, acc[i][1]);
            acc[i][2] = fmaf(fv[i].x, w0.z, acc[i][2]);
            acc[i][3] = fmaf(fv[i].x, w0.w, acc[i][3]);
            acc[i][0] = fmaf(fv[i].y, w1.x, acc[i][0]);
            acc[i][1] = fmaf(fv[i].y, w1.y, acc[i][1]);
            acc[i][2] = fmaf(fv[i].y, w1.z, acc[i][2]);
            acc[i][3] = fmaf(fv[i].y, w1.w, acc[i][3]);
            acc[i][0] = fmaf(fv[i].z, w2.x, acc[i][0]);
            acc[i][1] = fmaf(fv[i].z, w2.y, acc[i][1]);
            acc[i][2] = fmaf(fv[i].z, w2.z, acc[i][2]);
            acc[i][3] = fmaf(fv[i].z, w2.w, acc[i][3]);
            acc[i][0] = fmaf(fv[i].w, w3.x, acc[i][0]);
            acc[i][1] = fmaf(fv[i].w, w3.y, acc[i][1]);
            acc[i][2] = fmaf(fv[i].w, w3.z, acc[i][2]);
            acc[i][3] = fmaf(fv[i].w, w3.w, acc[i][3]);
        }
    }

    {
        int r = tid >> 1, c = tid & 1;
        const float4* fr = fs4 + r * FSTRIDE4;
        const float4* gw = (const float4*)fgw + c * 64;
        float s = 0.f;
        #pragma unroll 4
        for (int fe4 = 0; fe4 < 64; ++fe4) {
            float4 a = fr[fe4];
            float4 b = __ldg(&gw[fe4]);
            s += a.x * b.x + a.y * b.y + a.z * b.z + a.w * b.w;
        }
        gg[r * 2 + c] = s + __ldg(&fgb[c]);
    }
    __syncthreads();

    float* raw = fs;
    #pragma unroll
    for (int i = 0; i < 8; ++i)
        #pragma unroll
        for (int j = 0; j < 4; ++j)
            raw[(r0 + i) * WSTRIDE + (o0 + j)] = acc[i][j] + __ldg(&ckb[o0 + j]);
    __syncthreads();

    {
        int r = tid >> 1, c = tid & 1;
        float ss = 0.f;
        #pragma unroll
        for (int i = 0; i < 32; ++i) {
            float v = raw[r * WSTRIDE + c * 32 + i];
            ss += v * v;
        }
        invn[r * 2 + c] = 1.0f / (1e-6f + sqrtf(ss));
        gain[r * 2 + c] = expf(GAIN_A * tanhf(gg[r * 2 + c]));
    }
    __syncthreads();

    for (int idx = tid; idx < TBF * NFILT; idx += 256) {
        int r = idx >> 6, o = idx & 63;
        int co = o >> 5;
        float v = SG * raw[r * WSTRIDE + o] * invn[r * 2 + co];
        if ((o & 15) == 7) v += OMSG;
        g_w[(size_t)(bf0 + r) * NFILT + o] = v * gain[r * 2 + co];
    }
}

// ===========================================================================
// Kernel B v3: warp = frame; lane computes 5 consecutive head outputs from a
// 20-float register window, processed PER-CIN (one window live at a time).
// Lanes 0..7 (output positions 0..39) additionally run the prev-frame filter
// over the SAME register window (tail == head window identity), blend inline.
// No smem exchange, no second window. FPB=10 frames/block, 320 threads,
// min 3 blocks/SM -> regs <= 68 -> ~47% occupancy.
// ===========================================================================
#define FPB  10
#define NEED (FPB * FRAME + 16)      // 1616
#define XPAD 1624

__global__ void __launch_bounds__(FPB * 32, 3) conv_kernel(
    const float* __restrict__ x,     // (B, CIN, NSAMP)
    const float* __restrict__ owin,  // (40,)
    float* __restrict__ out)         // (B, COUT, NSAMP)
{
    __shared__ __align__(16) float xs[CIN][XPAD];         // origin f0*160-16
    __shared__ __align__(16) float wsm[FPB + 1][NFILT];   // [0] = f0-1 filter
    __shared__ __align__(16) float ob[FPB][COUT][FRAME];
    __shared__ float w1s[OVL], w2s[OVL];

    const int NT = FPB * 32;
    int f0 = blockIdx.x * FPB;
    int b  = blockIdx.y;
    int tid  = threadIdx.x;
    int lane = tid & 31;
    int w    = tid >> 5;

    // ---- x window: float4 coalesced (scalar-zero prefix only for f0==0) ----
    const float* xb = x + (size_t)b * CIN * NSAMP;
    if (f0 == 0) {
        if (tid < 16) { xs[0][tid] = 0.f; xs[1][tid] = 0.f; }
        const int N4 = (NEED - 16) / 4;                   // 400
        for (int i = tid; i < CIN * N4; i += NT) {
            int ci = i / N4, q = i - ci * N4;
            ((float4*)(xs[ci] + 16))[q] =
                ((const float4*)(xb + (size_t)ci * NSAMP))[q];
        }
    } else {
        int base = f0 * FRAME - 16;                       // 16B-aligned
        const int N4 = NEED / 4;                          // 404
        for (int i = tid; i < CIN * N4; i += NT) {
            int ci = i / N4, q = i - ci * N4;
            ((float4*)xs[ci])[q] =
                ((const float4*)(xb + (size_t)ci * NSAMP + base))[q];
        }
    }
    // ---- filters for frames f0-1 .. f0+FPB-1 ----
    for (int i = tid; i < (FPB + 1) * NFILT; i += NT) {
        int fi = f0 - 1 + (i >> 6);
        wsm[0][i] = (fi >= 0) ? g_w[((size_t)b * NF + fi) * NFILT + (i & 63)]
                              : 0.f;
    }
    if (tid < OVL) {
        w2s[tid] = owin[tid];
        w1s[tid] = owin[OVL - 1 - tid];
    }
    __syncthreads();

    int j0 = 5 * lane;
    int sb = w * FRAME + 16;          // xs index of this frame's sample 0

    float a0[5] = {0,0,0,0,0}, a1[5] = {0,0,0,0,0};
    float p0[5] = {0,0,0,0,0}, p1[5] = {0,0,0,0,0};

    const float4* wc = (const float4*)wsm[w + 1];
    const float4* wp = (const float4*)wsm[w];

    #pragma unroll
    for (int ci = 0; ci < CIN; ++ci) {
        float xw[20];
        #pragma unroll
        for (int i = 0; i < 20; ++i)
            xw[i] = xs[ci][sb + j0 - 15 + i];

        #pragma unroll
        for (int kc = 0; kc < 4; ++kc) {
            float4 c0 = wc[ci * 4 + kc];          // co=0, taps 4kc..4kc+3
            float4 c1 = wc[8 + ci * 4 + kc];      // co=1
            float wk0[4] = {c0.x, c0.y, c0.z, c0.w};
            float wk1[4] = {c1.x, c1.y, c1.z, c1.w};
            #pragma unroll
            for (int kk = 0; kk < 4; ++kk) {
                int k = 4 * kc + kk;
                #pragma unroll
                for (int m = 0; m < 5; ++m) {
                    float xv = xw[m + 15 - k];
                    a0[m] = fmaf(wk0[kk], xv, a0[m]);
                    a1[m] = fmaf(wk1[kk], xv, a1[m]);
                }
            }
        }
        if (lane < 8) {                            // overlap lanes: tail conv
            #pragma unroll
            for (int kc = 0; kc < 4; ++kc) {
                float4 c0 = wp[ci * 4 + kc];
                float4 c1 = wp[8 + ci * 4 + kc];
                float wk0[4] = {c0.x, c0.y, c0.z, c0.w};
                float wk1[4] = {c1.x, c1.y, c1.z, c1.w};
                #pragma unroll
                for (int kk = 0; kk < 4; ++kk) {
                    int k = 4 * kc + kk;
                    #pragma unroll
                    for (int m = 0; m < 5; ++m) {
                        float xv = xw[m + 15 - k];
                        p0[m] = fmaf(wk0[kk], xv, p0[m]);
                        p1[m] = fmaf(wk1[kk], xv, p1[m]);
                    }
                }
            }
        }
    }

    // ---- blend + stage ----
    if (lane < 8) {
        #pragma unroll
        for (int m = 0; m < 5; ++m) {
            int j = j0 + m;
            ob[w][0][j] = w1s[j] * a0[m] + w2s[j] * p0[m];
            ob[w][1][j] = w1s[j] * a1[m] + w2s[j] * p1[m];
        }
    } else {
        #pragma unroll
        for (int m = 0; m < 5; ++m) {
            int j = j0 + m;
            ob[w][0][j] = a0[m];
            ob[w][1][j] = a1[m];
        }
    }
    __syncwarp();

    // ---- coalesced float4 store ----
    int f = f0 + w;
    #pragma unroll
    for (int co = 0; co < COUT; ++co) {
        float4* op = (float4*)(out + (size_t)b * COUT * NSAMP
                               + (size_t)co * NSAMP + (size_t)f * FRAME);
        const float4* obp = (const float4*)ob[w][co];
        #pragma unroll
        for (int i = lane; i < FRAME / 4; i += 32)
            op[i] = obp[i];
    }
}

extern "C" void kernel_launch(void* const* d_in, const int* in_sizes, int n_in,
                              void* d_out, int out_size)
{
    const float* x    = (const float*)d_in[0];
    const float* feat = (const float*)d_in[1];
    const float* ckw  = (const float*)d_in[2];
    const float* ckb  = (const float*)d_in[3];
    const float* fgw  = (const float*)d_in[4];
    const float* fgb  = (const float*)d_in[5];
    const float* ow   = (const float*)d_in[6];
    float* out = (float*)d_out;

    int smem = (TBF * 260 + 256 * WSTRIDE + 3 * TBF * 2) * (int)sizeof(float);
    static int configured = 0;
    if (!configured) {
        cudaFuncSetAttribute(filt_kernel,
                             cudaFuncAttributeMaxDynamicSharedMemorySize, smem);
        configured = 1;
    }

    filt_kernel<<<NB * NF / TBF, 256, smem>>>(feat, ckw, ckb, fgw, fgb);
    conv_kernel<<<dim3(NF / FPB, NB), FPB * 32>>>(x, ow, out);
}